// round 16
// baseline (speedup 1.0000x reference)
#include <cuda_runtime.h>

#define Bb 16
#define Ss 4096
#define Hh 1024
#define NN 2048
#define DWw 50
#define OD (Hh + DWw)   // 1074

#define WPB 16                // words per block (proven granularity)
#define NGRP (NN / WPB)       // 128 groups per batch
#define NCH_W 8               // lastw chunks per batch
#define RCH 8                 // reduce chunks per batch (16 groups each; 9 atomic writers)
#define GPC (NGRP / RCH)      // 16 groups per reduce chunk

__device__ float g_part[Bb][NGRP][Hh];    // per-block prefix maxes (8MB)
__device__ float g_lastw[NCH_W][Bb][64];  // lastw partials (plain stores)

__device__ __forceinline__ void atomicMaxF(float* addr, float val) {
    if (val >= 0.f) atomicMax((int*)addr, __float_as_int(val));
    else            atomicMin((unsigned int*)addr, __float_as_uint(val));
}

__device__ __forceinline__ float4 fmax4(float4 a, float4 b) {
    a.x = fmaxf(a.x, b.x); a.y = fmaxf(a.y, b.y);
    a.z = fmaxf(a.z, b.z); a.w = fmaxf(a.w, b.w);
    return a;
}

// Pass 1: 16 consecutive words per block; span boundaries via 17 parallel
// binary searches over sorted seg_ids (L2-resident, hidden by streaming).
// Prefix rows (< ns-1) fold into a register -> plain store to g_part.
// The block owning word ns-1 initializes that row's ctx part to -inf so
// pass 2 can atomic-fold into it. lastw chunks plain-store partials.
__global__ void __launch_bounds__(256)
fused_kernel(const float* __restrict__ ctx,
             const float* __restrict__ wemb,
             const int* __restrict__ seg,
             const int* __restrict__ ns_arr,
             float* __restrict__ out) {
    int bx = blockIdx.x;
    int b  = blockIdx.y;
    int t  = threadIdx.x;            // 0..255, owns channels 4t..4t+3
    int ns = ns_arr[b];
    float ninf = __int_as_float(0xFF800000);

    if (bx < NGRP) {
        int n0 = bx * WPB;
        __shared__ int sbound[WPB + 1];
        if (t <= WPB) {
            // lower_bound(seg[b], n0+t): first s with seg[s] >= key
            int key = n0 + t;
            const int* s = seg + (long)b * Ss;
            int lo = 0, hi = Ss;
#pragma unroll
            for (int it = 0; it < 12; it++) {   // 2^12 = 4096 = Ss
                int m = (lo + hi) >> 1;
                if (__ldg(s + m) < key) lo = m + 1; else hi = m;
            }
            sbound[t] = lo;
        }
        __syncthreads();

        float4 blockAcc = make_float4(ninf, ninf, ninf, ninf);

        for (int w = 0; w < WPB; w++) {
            int n = n0 + w;
            float* orow = out + ((long)b * NN + n) * OD;
            float2* o2 = (float2*)orow;   // rows 8B-aligned (4296B stride)

            if (n >= ns) {                // padding: zero-fill (out is poisoned)
                for (int i = t; i < OD / 2; i += 256) o2[i] = make_float2(0.f, 0.f);
                continue;
            }
            if (n == ns - 1) {            // special row: init ctx part to -inf
                float2 nv = make_float2(ninf, ninf);
                o2[2 * t]     = nv;
                o2[2 * t + 1] = nv;
                continue;
            }

            int start = sbound[w];
            int end   = sbound[w + 1];
            int cnt = end - start;
            int k = ns - 1 - start;       // rows counting toward last_ctx
            k = max(0, min(cnt, k));

            const float4* crow = (const float4*)(ctx + ((long)b * Ss + start) * Hh);
            float4 acc = crow[t];
            int r = 1;
            if (k > 0) {
#pragma unroll 4
                for (; r < k; r++) acc = fmax4(acc, crow[(long)r * (Hh / 4) + t]);
                blockAcc = fmax4(blockAcc, acc);
            }
#pragma unroll 4
            for (; r < cnt; r++) acc = fmax4(acc, crow[(long)r * (Hh / 4) + t]);

            o2[2 * t]     = make_float2(acc.x, acc.y);
            o2[2 * t + 1] = make_float2(acc.z, acc.w);
            if (t < DWw) orow[Hh + t] = wemb[((long)b * NN + n) * DWw + t];
        }
        ((float4*)g_part[b][bx])[t] = blockAcc;   // plain store
        return;
    }

    // lastw: max over words 0..ns-1 of word_emb -> plain-store partial
    int rc = bx - NGRP;
    if (t >= DWw) return;
    int per = (ns + NCH_W - 1) / NCH_W;
    int r0 = rc * per;
    int r1 = min(ns, r0 + per);
    float acc = ninf;
    if (r0 < r1) {
        acc = wemb[((long)b * NN + r0) * DWw + t];
#pragma unroll 4
        for (int r = r0 + 1; r < r1; r++)
            acc = fmaxf(acc, wemb[((long)b * NN + r) * DWw + t]);
    }
    g_lastw[rc][b][t] = acc;
}

// Pass 2: 8x16 blocks. All 16 float4 loads are front-batched into named
// registers (MLP_p1 = 16, ~64KB in flight per block) before the tree fold,
// then one atomic fold per channel into the last-word row (9 writers max).
// Chunk 0 writes the word-emb part from the lastw partials.
__global__ void __launch_bounds__(256, 1)
reduce_kernel(const int* __restrict__ ns_arr,
              float* __restrict__ out) {
    int c = blockIdx.x;              // 0..RCH-1
    int b = blockIdx.y;
    int t = threadIdx.x;             // 0..255

    float4 v[GPC];
    int g0 = c * GPC;
#pragma unroll
    for (int i = 0; i < GPC; i++)     // 16 independent LDG.128, front-batched
        v[i] = ((const float4*)g_part[b][g0 + i])[t];
#pragma unroll
    for (int s = GPC / 2; s > 0; s >>= 1)
#pragma unroll
        for (int i = 0; i < s; i++)
            v[i] = fmax4(v[i], v[i + s]);

    int n = ns_arr[b] - 1;
    float* orow = out + ((long)b * NN + n) * OD;
    float* dst = orow + 4 * t;
    atomicMaxF(dst + 0, v[0].x);
    atomicMaxF(dst + 1, v[0].y);
    atomicMaxF(dst + 2, v[0].z);
    atomicMaxF(dst + 3, v[0].w);

    if (c == 0 && t < DWw) {
        float w = g_lastw[0][b][t];
#pragma unroll
        for (int k = 1; k < NCH_W; k++) w = fmaxf(w, g_lastw[k][b][t]);
        orow[Hh + t] = w;
    }
}

extern "C" void kernel_launch(void* const* d_in, const int* in_sizes, int n_in,
                              void* d_out, int out_size) {
    const float* ctx  = (const float*)d_in[0];   // [B, S, H]
    const float* wemb = (const float*)d_in[1];   // [B, N, DW]
    const int*   seg  = (const int*)d_in[2];     // [B, S]
    const int*   ns   = (const int*)d_in[3];     // [B]
    float* out = (float*)d_out;                  // [B, N, H+DW]

    fused_kernel<<<dim3(NGRP + NCH_W, Bb), 256>>>(ctx, wemb, seg, ns, out);
    reduce_kernel<<<dim3(RCH, Bb), 256>>>(ns, out);
}

// round 17
// speedup vs baseline: 1.0782x; 1.0782x over previous
#include <cuda_runtime.h>

#define Bb 16
#define Ss 4096
#define Hh 1024
#define NN 2048
#define DWw 50
#define OD (Hh + DWw)   // 1074

#define WPB 16                // words per block (proven granularity)
#define NGRP (NN / WPB)       // 128 groups per batch
#define NCH_W 8               // lastw chunks per batch

__device__ int g_start[Bb][NN + 1];

__device__ __forceinline__ void atomicMaxF(float* addr, float val) {
    if (val >= 0.f) atomicMax((int*)addr, __float_as_int(val));
    else            atomicMin((unsigned int*)addr, __float_as_uint(val));
}

__device__ __forceinline__ float4 fmax4(float4 a, float4 b) {
    a.x = fmaxf(a.x, b.x); a.y = fmaxf(a.y, b.y);
    a.z = fmaxf(a.z, b.z); a.w = fmaxf(a.w, b.w);
    return a;
}

// Pass 1: word-span boundaries from sorted seg_ids (int4 vectorized), and
// init the ENTIRE last-word output row (ctx part + word part) to -inf so
// fused blocks can atomic-fold into it.
__global__ void prep_kernel(const int* __restrict__ seg,
                            const int* __restrict__ ns_arr,
                            float* __restrict__ out) {
    int b = blockIdx.x;
    int i = blockIdx.y * 256 + threadIdx.x;          // int4 index 0..1023
    const int4* s4 = (const int4*)(seg + (long)b * Ss);
    int4 v = s4[i];
    int s = i * 4;
    int prev = (s == 0) ? -1 : __ldg(seg + (long)b * Ss + s - 1);
    if (v.x != prev) g_start[b][v.x] = s;
    if (v.y != v.x)  g_start[b][v.y] = s + 1;
    if (v.z != v.y)  g_start[b][v.z] = s + 2;
    if (v.w != v.z)  g_start[b][v.w] = s + 3;
    if (s + 3 == Ss - 1) g_start[b][v.w + 1] = Ss;   // sentinel end

    if (blockIdx.y == 0) {
        float ninf = __int_as_float(0xFF800000);
        int n = ns_arr[b] - 1;
        float* orow = out + ((long)b * NN + n) * OD;
        for (int k = threadIdx.x; k < OD; k += 256) orow[k] = ninf;
    }
}

// Pass 2 (final): 16 consecutive words per block, contiguous ctx streaming
// + concat. Prefix rows (< ns-1) fold into blockAcc; blocks that have any
// prefix rows atomic-fold blockAcc straight into the last-word row (~48
// writers/address, fully overlapped with streaming — no g_part, no reduce
// kernel). lastw chunks atomic into the row's word-emb part.
__global__ void __launch_bounds__(256)
fused_kernel(const float* __restrict__ ctx,
             const float* __restrict__ wemb,
             const int* __restrict__ ns_arr,
             float* __restrict__ out) {
    int bx = blockIdx.x;
    int b  = blockIdx.y;
    int t  = threadIdx.x;            // 0..255, owns channels 4t..4t+3
    int ns = ns_arr[b];
    float ninf = __int_as_float(0xFF800000);

    if (bx < NGRP) {
        int n0 = bx * WPB;
        __shared__ int sbound[WPB + 1];
        if (t <= WPB) sbound[t] = g_start[b][min(n0 + t, NN)];
        __syncthreads();

        float4 blockAcc = make_float4(ninf, ninf, ninf, ninf);
        bool contrib = (sbound[0] < ns - 1) && (n0 < ns - 1);

        for (int w = 0; w < WPB; w++) {
            int n = n0 + w;
            float* orow = out + ((long)b * NN + n) * OD;
            float2* o2 = (float2*)orow;   // rows 8B-aligned (4296B stride)

            if (n >= ns) {                // padding: zero-fill (out is poisoned)
                for (int i = t; i < OD / 2; i += 256) o2[i] = make_float2(0.f, 0.f);
                continue;
            }
            if (n == ns - 1) continue;    // special row: prep init + atomics

            int start = sbound[w];
            int end   = sbound[w + 1];
            int cnt = end - start;
            int k = ns - 1 - start;       // rows counting toward last_ctx
            k = max(0, min(cnt, k));

            const float4* crow = (const float4*)(ctx + ((long)b * Ss + start) * Hh);
            float4 acc = crow[t];
            int r = 1;
            if (k > 0) {
#pragma unroll 4
                for (; r < k; r++) acc = fmax4(acc, crow[(long)r * (Hh / 4) + t]);
                blockAcc = fmax4(blockAcc, acc);
            }
#pragma unroll 4
            for (; r < cnt; r++) acc = fmax4(acc, crow[(long)r * (Hh / 4) + t]);

            o2[2 * t]     = make_float2(acc.x, acc.y);
            o2[2 * t + 1] = make_float2(acc.z, acc.w);
            if (t < DWw) orow[Hh + t] = wemb[((long)b * NN + n) * DWw + t];
        }

        if (contrib) {                    // overlapped fold into special row
            float* dst = out + ((long)b * NN + ns - 1) * OD + 4 * t;
            atomicMaxF(dst + 0, blockAcc.x);
            atomicMaxF(dst + 1, blockAcc.y);
            atomicMaxF(dst + 2, blockAcc.z);
            atomicMaxF(dst + 3, blockAcc.w);
        }
        return;
    }

    // lastw: max over words 0..ns-1 of word_emb -> atomics into out row
    int rc = bx - NGRP;
    if (t >= DWw) return;
    int per = (ns + NCH_W - 1) / NCH_W;
    int r0 = rc * per;
    int r1 = min(ns, r0 + per);
    if (r0 >= r1) return;
    float acc = wemb[((long)b * NN + r0) * DWw + t];
#pragma unroll 4
    for (int r = r0 + 1; r < r1; r++) {
        acc = fmaxf(acc, wemb[((long)b * NN + r) * DWw + t]);
    }
    atomicMaxF(out + ((long)b * NN + ns - 1) * OD + Hh + t, acc);
}

extern "C" void kernel_launch(void* const* d_in, const int* in_sizes, int n_in,
                              void* d_out, int out_size) {
    const float* ctx  = (const float*)d_in[0];   // [B, S, H]
    const float* wemb = (const float*)d_in[1];   // [B, N, DW]
    const int*   seg  = (const int*)d_in[2];     // [B, S]
    const int*   ns   = (const int*)d_in[3];     // [B]
    float* out = (float*)d_out;                  // [B, N, H+DW]

    prep_kernel<<<dim3(Bb, 4), 256>>>(seg, ns, out);
    fused_kernel<<<dim3(NGRP + NCH_W, Bb), 256>>>(ctx, wemb, ns, out);
}